// round 6
// baseline (speedup 1.0000x reference)
#include <cuda_runtime.h>

typedef unsigned int u32;
typedef unsigned long long u64;

#define RANKS 4
#define OCN   128
#define ICN   128
#define HH    56
#define WW    56
#define HW    3136
#define NST   36
#define KC    32
#define NTILES 1792
#define NCTA   148

#define B_STAGE_W (KC*512)            // 16384 words = 65536 B per stage
#define SM_B0 1024
#define SM_A0 (1024 + 3*65536)        // 197632
#define SM_A1 (SM_A0 + 9216)
#define SM_PART (1024 + 2*65536)      // aliases B buffer 2 (free at tile end)
#define SM_TOTAL (SM_A1 + 9216)       // 216064

__device__ __align__(16) u32   g_wB[NST * B_STAGE_W];  // tf32, pre-swizzled smem image
__device__ __align__(16) float g_cw[RANKS * HW];       // softmax combine weights

// ---------------- helpers ----------------
__device__ __forceinline__ u32 smem_u32(const void* p) {
    u32 a;
    asm("{ .reg .u64 t; cvta.to.shared.u64 t, %1; cvt.u32.u64 %0, t; }" : "=r"(a) : "l"(p));
    return a;
}
__device__ __forceinline__ u32 cvt_tf32(float v) {
    u32 r;
    asm("cvt.rna.tf32.f32 %0, %1;" : "=r"(r) : "f"(v));
    return r;
}
__device__ __forceinline__ void mbar_init(u32 addr, u32 cnt) {
    asm volatile("mbarrier.init.shared.b64 [%0], %1;" :: "r"(addr), "r"(cnt) : "memory");
}
__device__ __forceinline__ void mbar_expect_tx(u32 addr, u32 bytes) {
    asm volatile("mbarrier.arrive.expect_tx.shared.b64 _, [%0], %1;" :: "r"(addr), "r"(bytes) : "memory");
}
__device__ __forceinline__ void mbar_wait(u32 addr, int phase) {
    asm volatile(
        "{\n\t.reg .pred P;\n"
        "WL_%=:\n\t"
        "mbarrier.try_wait.parity.acquire.cta.shared::cta.b64 P, [%0], %1, 0x989680;\n\t"
        "@P bra.uni WD_%=;\n\t"
        "bra.uni WL_%=;\n\t"
        "WD_%=:\n\t}"
        :: "r"(addr), "r"((u32)phase) : "memory");
}
__device__ __forceinline__ void bulk_copy(u32 dst, const void* src, u32 bytes, u32 mbar) {
    asm volatile(
        "cp.async.bulk.shared::cluster.global.mbarrier::complete_tx::bytes [%0], [%1], %2, [%3];"
        :: "r"(dst), "l"(src), "r"(bytes), "r"(mbar) : "memory");
}
__device__ __forceinline__ void mma_tf32(float& d0, float& d1, float& d2, float& d3,
                                         u32 a0, u32 a1, u32 a2, u32 a3, u32 b0, u32 b1) {
    asm volatile(
        "mma.sync.aligned.m16n8k8.row.col.f32.tf32.tf32.f32 "
        "{%0,%1,%2,%3}, {%4,%5,%6,%7}, {%8,%9}, {%0,%1,%2,%3};"
        : "+f"(d0), "+f"(d1), "+f"(d2), "+f"(d3)
        : "r"(a0), "r"(a1), "r"(a2), "r"(a3), "r"(b0), "r"(b1));
}

// ---------------- prep kernels ----------------
__global__ void prep_cw_kernel(const float* __restrict__ cw_row,
                               const float* __restrict__ cw_col) {
    int idx = blockIdx.x * blockDim.x + threadIdx.x;
    if (idx >= HW) return;
    int y = idx / WW, x = idx % WW;
    float v0 = cw_row[0 * HH + y] + cw_col[0 * WW + x];
    float v1 = cw_row[1 * HH + y] + cw_col[1 * WW + x];
    float v2 = cw_row[2 * HH + y] + cw_col[2 * WW + x];
    float v3 = cw_row[3 * HH + y] + cw_col[3 * WW + x];
    float m = fmaxf(fmaxf(v0, v1), fmaxf(v2, v3));
    float e0 = expf(v0 - m), e1 = expf(v1 - m), e2 = expf(v2 - m), e3 = expf(v3 - m);
    float inv = 1.0f / (e0 + e1 + e2 + e3);
    g_cw[0 * HW + idx] = e0 * inv;
    g_cw[1 * HW + idx] = e1 * inv;
    g_cw[2 * HW + idx] = e2 * inv;
    g_cw[3 * HW + idx] = e3 * inv;
}

// Weights -> tf32 in the exact swizzled smem image.
// Stage s: tap = s>>2 (ky*3+kx), ic = (s&3)*32 + kk.  n = rank*128 + oc.
// smem word (k-row kk, col n): kk*512 + (n ^ ((kk&3)<<3))
__global__ void prep_wB_kernel(const float* __restrict__ w) {
    int idx = blockIdx.x * blockDim.x + threadIdx.x;
    if (idx >= NST * B_STAGE_W) return;
    int n  = idx & 511;
    int kk = (idx >> 9) & 31;
    int s  = idx >> 14;
    int r  = n >> 7, oc = n & 127;
    int tap = s >> 2;
    int ic  = ((s & 3) << 5) + kk;
    float v = w[(((size_t)r * OCN + oc) * ICN + ic) * 9 + tap];
    g_wB[(size_t)s * B_STAGE_W + kk * 512 + (n ^ ((kk & 3) << 3))] = cvt_tf32(v);
}

// ---------------- main persistent mma kernel ----------------
// grid 148 CTAs x 512 threads; CTA c handles tiles c, c+148, ... (< 1792).
// tile -> bb = tile/56, y = tile%56.  16 warps = 4 warp_m x 4 warp_n(=rank).
__global__ __launch_bounds__(512, 1)
void conv_mma_kernel(const float* __restrict__ x, float* __restrict__ out,
                     const float* __restrict__ b_row, const float* __restrict__ b_col,
                     const float* __restrict__ b_ch) {
    extern __shared__ char smem[];
    const u32 sbase = smem_u32(smem);
    const int tid = threadIdx.x;
    const int wid = tid >> 5, lane = tid & 31;
    const int warp_m = wid & 3, warp_n = wid >> 2;
    const int g = lane >> 2, t = lane & 3;
    const int c = blockIdx.x;

    const int ntile = (NTILES - c + NCTA - 1) / NCTA;
    const int total = ntile * NST;

    if (tid == 0) {
        mbar_init(sbase + 0, 1);
        mbar_init(sbase + 8, 1);
        mbar_init(sbase + 16, 1);
    }
    __syncthreads();

    // fragment / staging constants
    const int arow0 = (warp_m * 16 + g) * 36;
    const int arow1 = arow0 + 8 * 36;
    const int bcol = warp_n * 128 + g;
    const int txor = t << 3;
    const int apx = tid & 63;          // A-staging pixel (const per thread)
    const int akk = tid >> 6;          // A-staging k base (i adds 8)

    float acc[16][4];

    // ---- prologue: TMA stages 0,1 ; stageA(0) ----
    if (tid == 0) {
        mbar_expect_tx(sbase + 0, 65536);
        bulk_copy(sbase + SM_B0, g_wB, 65536, sbase + 0);
        mbar_expect_tx(sbase + 8, 65536);
        bulk_copy(sbase + SM_B0 + 65536, g_wB + B_STAGE_W, 65536, sbase + 8);
    }
    {
        const int gt = c, y0 = gt % 56, bb0 = gt / 56;
        const float* xb = x + (size_t)bb0 * ICN * HW;   // stage 0: tap 4? no, tap = 0
        // stage 0: tap=0 -> dy=-1, dx=-1, ic0=0
        u32* Ab = (u32*)(smem + SM_A0);
        const int gy = y0 - 1;
        const bool rowok = gy >= 0;
#pragma unroll
        for (int i = 0; i < 4; i++) {
            const int kk = i * 8 + akk;
            const int gx = apx - 1;
            float v = 0.0f;
            if (rowok && gx >= 0) v = xb[(size_t)kk * HW + gy * WW + gx];
            Ab[apx * 36 + kk] = cvt_tf32(v);
        }
    }

    // ---- main loop over global stages ----
    for (int gs = 0; gs < total; gs++) {
        const int s = gs % NST;
        const int gt = c + (gs / NST) * NCTA;
        const int y = gt % 56, bb = gt / 56;

        mbar_wait(sbase + (gs % 3) * 8, (gs / 3) & 1);
        __syncthreads();

        // prefetch B for gs+2
        if (tid == 0 && gs + 2 < total) {
            const int s2 = (gs + 2) % NST;
            const u32 mb = sbase + ((gs + 2) % 3) * 8;
            mbar_expect_tx(mb, 65536);
            bulk_copy(sbase + SM_B0 + ((gs + 2) % 3) * 65536,
                      g_wB + (size_t)s2 * B_STAGE_W, 65536, mb);
        }

        // early LDG for A(gs+1)
        float av[4];
        const bool doA = (gs + 1 < total);
        if (doA) {
            const int gs1 = gs + 1;
            const int s1 = gs1 % NST;
            const int gt1 = c + (gs1 / NST) * NCTA;
            const int y1 = gt1 % 56, bb1 = gt1 / 56;
            const int tap = s1 >> 2;
            const int dy = tap / 3 - 1, dx = tap % 3 - 1;
            const int ic0 = (s1 & 3) << 5;
            const int gy = y1 + dy, gx = apx + dx;
            const bool ok = (unsigned)gy < 56u && (unsigned)gx < 56u;
            const float* src = x + (size_t)bb1 * ICN * HW + (size_t)ic0 * HW + gy * WW + gx;
#pragma unroll
            for (int i = 0; i < 4; i++)
                av[i] = ok ? src[(size_t)(i * 8 + akk) * HW] : 0.0f;
        }

        if (s == 0) {
#pragma unroll
            for (int i = 0; i < 16; i++)
#pragma unroll
                for (int j = 0; j < 4; j++) acc[i][j] = 0.0f;
        }

        // ---- MMAs for stage gs ----
        const u32* Bb = (const u32*)(smem + SM_B0 + (gs % 3) * 65536);
        const u32* Ab = (const u32*)(smem + SM_A0 + (gs & 1) * 9216);
#pragma unroll
        for (int ks = 0; ks < 4; ks++) {
            const int ak = ks * 8 + t;
            u32 a0 = Ab[arow0 + ak];
            u32 a1 = Ab[arow1 + ak];
            u32 a2 = Ab[arow0 + ak + 4];
            u32 a3 = Ab[arow1 + ak + 4];
            const u32* b0p = Bb + (ks * 8 + t) * 512 + bcol;
            const u32* b1p = b0p + 4 * 512;
#pragma unroll
            for (int nt = 0; nt < 16; nt++) {
                const int off = (nt << 3) ^ txor;
                mma_tf32(acc[nt][0], acc[nt][1], acc[nt][2], acc[nt][3],
                         a0, a1, a2, a3, b0p[off], b1p[off]);
            }
        }

        // store staged A(gs+1)
        if (doA) {
            u32* Ab1 = (u32*)(smem + SM_A0 + ((gs + 1) & 1) * 9216);
#pragma unroll
            for (int i = 0; i < 4; i++)
                Ab1[apx * 36 + i * 8 + akk] = cvt_tf32(av[i]);
        }

        // ---- epilogue at tile end ----
        if (s == NST - 1) {
            __syncthreads();           // all warps done with MMAs (and B buf 2 reads)
            float* part = (float*)(smem + SM_PART);
            const int px0 = warp_m * 16 + g, px1 = px0 + 8;
            const float cw0 = g_cw[warp_n * HW + y * WW + px0];
            const float cw1 = (px1 < 56) ? g_cw[warp_n * HW + y * WW + px1] : 0.0f;
#pragma unroll
            for (int pass = 0; pass < 4; pass++) {
                if (warp_n == pass) {
#pragma unroll
                    for (int nt = 0; nt < 16; nt++) {
                        const int oc = nt * 8 + 2 * t;
                        float* p0 = &part[px0 * 132 + oc];
                        float* p1 = &part[px1 * 132 + oc];
                        if (pass == 0) {
                            p0[0] = cw0 * acc[nt][0]; p0[1] = cw0 * acc[nt][1];
                            p1[0] = cw1 * acc[nt][2]; p1[1] = cw1 * acc[nt][3];
                        } else {
                            p0[0] += cw0 * acc[nt][0]; p0[1] += cw0 * acc[nt][1];
                            p1[0] += cw1 * acc[nt][2]; p1[1] += cw1 * acc[nt][3];
                        }
                    }
                }
                __syncthreads();
            }
            const float br = b_row[y];
            for (int idx = tid; idx < OCN * 56; idx += 512) {
                const int oc = idx / 56, xx = idx - oc * 56;
                out[((size_t)(bb * OCN + oc) * HH + y) * WW + xx] =
                    part[xx * 132 + oc] + br + b_col[xx] + b_ch[oc];
            }
            // next iteration's top wait+syncthreads protects buf2 reuse
        }
    }
}

// ---------------- launch ----------------
extern "C" void kernel_launch(void* const* d_in, const int* in_sizes, int n_in,
                              void* d_out, int out_size) {
    const float* x      = (const float*)d_in[0];  // [32,128,56,56]
    const float* w      = (const float*)d_in[1];  // [4,128,128,3,3]
    const float* cw_row = (const float*)d_in[2];  // [4,56,1]
    const float* cw_col = (const float*)d_in[3];  // [4,1,56]
    const float* b_row  = (const float*)d_in[4];  // [1,1,56,1]
    const float* b_col  = (const float*)d_in[5];  // [1,1,1,56]
    const float* b_ch   = (const float*)d_in[6];  // [1,128,1,1]
    float* out = (float*)d_out;

    cudaFuncSetAttribute(conv_mma_kernel,
                         cudaFuncAttributeMaxDynamicSharedMemorySize, SM_TOTAL);

    prep_cw_kernel<<<(HW + 255) / 256, 256>>>(cw_row, cw_col);
    prep_wB_kernel<<<(NST * B_STAGE_W + 255) / 256, 256>>>(w);
    conv_mma_kernel<<<NCTA, 512, SM_TOTAL>>>(x, out, b_row, b_col, b_ch);
}

// round 7
// speedup vs baseline: 1.6029x; 1.6029x over previous
#include <cuda_runtime.h>
#include <cuda_fp16.h>

typedef unsigned int u32;
typedef unsigned long long u64;

#define RANKS 4
#define OCN   128
#define ICN   128
#define HH    56
#define WW    56
#define HW    3136
#define NST   36
#define NTILES 1792
#define NCTA   148

#define B_STAGE_W 8192                 // 16 kpairs * 512 n  (u32 words) = 32 KB
#define B_STAGE_BYTES 32768
#define AP    20                       // A row stride in words (bank-exhaustive)
#define A_BUF_BYTES (64*AP*4)          // 5120

#define SM_B0 1024
#define SM_A0 (1024 + 3*B_STAGE_BYTES)         // 99328
#define SM_A1 (SM_A0 + A_BUF_BYTES)            // 104448
#define SM_PART (SM_A1 + A_BUF_BYTES)          // 109568
#define SM_TOTAL (SM_PART + 64*132*4)          // 143360

__device__ __align__(16) u32   g_wB[NST * B_STAGE_W];  // fp16x2, pre-swizzled smem image
__device__ __align__(16) float g_cw[RANKS * HW];       // softmax combine weights

// ---------------- helpers ----------------
__device__ __forceinline__ u32 smem_u32(const void* p) {
    u32 a;
    asm("{ .reg .u64 t; cvta.to.shared.u64 t, %1; cvt.u32.u64 %0, t; }" : "=r"(a) : "l"(p));
    return a;
}
__device__ __forceinline__ u32 pack_h2(float lo, float hi) {
    __half2 h = __floats2half2_rn(lo, hi);
    return *(u32*)&h;
}
__device__ __forceinline__ void mbar_init(u32 addr, u32 cnt) {
    asm volatile("mbarrier.init.shared.b64 [%0], %1;" :: "r"(addr), "r"(cnt) : "memory");
}
__device__ __forceinline__ void mbar_expect_tx(u32 addr, u32 bytes) {
    asm volatile("mbarrier.arrive.expect_tx.shared.b64 _, [%0], %1;" :: "r"(addr), "r"(bytes) : "memory");
}
__device__ __forceinline__ void mbar_wait(u32 addr, int phase) {
    asm volatile(
        "{\n\t.reg .pred P;\n"
        "WL_%=:\n\t"
        "mbarrier.try_wait.parity.acquire.cta.shared::cta.b64 P, [%0], %1, 0x989680;\n\t"
        "@P bra.uni WD_%=;\n\t"
        "bra.uni WL_%=;\n\t"
        "WD_%=:\n\t}"
        :: "r"(addr), "r"((u32)phase) : "memory");
}
__device__ __forceinline__ void bulk_copy(u32 dst, const void* src, u32 bytes, u32 mbar) {
    asm volatile(
        "cp.async.bulk.shared::cluster.global.mbarrier::complete_tx::bytes [%0], [%1], %2, [%3];"
        :: "r"(dst), "l"(src), "r"(bytes), "r"(mbar) : "memory");
}
__device__ __forceinline__ void mma_f16(float& d0, float& d1, float& d2, float& d3,
                                        u32 a0, u32 a1, u32 a2, u32 a3, u32 b0, u32 b1) {
    asm volatile(
        "mma.sync.aligned.m16n8k16.row.col.f32.f16.f16.f32 "
        "{%0,%1,%2,%3}, {%4,%5,%6,%7}, {%8,%9}, {%0,%1,%2,%3};"
        : "+f"(d0), "+f"(d1), "+f"(d2), "+f"(d3)
        : "r"(a0), "r"(a1), "r"(a2), "r"(a3), "r"(b0), "r"(b1));
}

// ---------------- prep kernels ----------------
__global__ void prep_cw_kernel(const float* __restrict__ cw_row,
                               const float* __restrict__ cw_col) {
    int idx = blockIdx.x * blockDim.x + threadIdx.x;
    if (idx >= HW) return;
    int y = idx / WW, x = idx % WW;
    float v0 = cw_row[0 * HH + y] + cw_col[0 * WW + x];
    float v1 = cw_row[1 * HH + y] + cw_col[1 * WW + x];
    float v2 = cw_row[2 * HH + y] + cw_col[2 * WW + x];
    float v3 = cw_row[3 * HH + y] + cw_col[3 * WW + x];
    float m = fmaxf(fmaxf(v0, v1), fmaxf(v2, v3));
    float e0 = expf(v0 - m), e1 = expf(v1 - m), e2 = expf(v2 - m), e3 = expf(v3 - m);
    float inv = 1.0f / (e0 + e1 + e2 + e3);
    g_cw[0 * HW + idx] = e0 * inv;
    g_cw[1 * HW + idx] = e1 * inv;
    g_cw[2 * HW + idx] = e2 * inv;
    g_cw[3 * HW + idx] = e3 * inv;
}

// Weights -> fp16 pairs in the exact swizzled smem image.
// Stage s: tap = s>>2, ic = (s&3)*32 + kk, kpair kp holds kk = 2kp, 2kp+1.
// smem word (kp, n): kp*512 + (n ^ ((kp&3)<<3)),  n = rank*128 + oc.
__global__ void prep_wB_kernel(const float* __restrict__ w) {
    int idx = blockIdx.x * blockDim.x + threadIdx.x;
    if (idx >= NST * B_STAGE_W) return;
    int n  = idx & 511;
    int kp = (idx >> 9) & 15;
    int s  = idx >> 13;
    int r  = n >> 7, oc = n & 127;
    int tap = s >> 2;
    int ic  = ((s & 3) << 5) + 2 * kp;
    const float* wp = w + (((size_t)r * OCN + oc) * ICN + ic) * 9 + tap;
    g_wB[(size_t)s * B_STAGE_W + kp * 512 + (n ^ ((kp & 3) << 3))] = pack_h2(wp[0], wp[9]);
}

// ---------------- main persistent mma kernel ----------------
// grid 148 CTAs x 512 threads; CTA c handles tiles c, c+148, ...
// tile -> bb = tile/56, y = tile%56.  16 warps = 4 warp_m x 4 warp_n(=rank).
__global__ __launch_bounds__(512, 1)
void conv_mma_kernel(const float* __restrict__ x, float* __restrict__ out,
                     const float* __restrict__ b_row, const float* __restrict__ b_col,
                     const float* __restrict__ b_ch) {
    extern __shared__ char smem[];
    const u32 sbase = smem_u32(smem);
    const int tid = threadIdx.x;
    const int wid = tid >> 5, lane = tid & 31;
    const int warp_m = wid & 3, warp_n = wid >> 2;
    const int g = lane >> 2, t = lane & 3;
    const int c = blockIdx.x;

    const int ntile = (NTILES - c + NCTA - 1) / NCTA;
    const int total = ntile * NST;

    if (tid == 0) {
        mbar_init(sbase + 0, 1);
        mbar_init(sbase + 8, 1);
        mbar_init(sbase + 16, 1);
    }
    __syncthreads();

    // fragment / staging constants
    const int arow0 = (warp_m * 16 + g) * AP;
    const int arow1 = arow0 + 8 * AP;
    const int bcol = warp_n * 128 + g;
    const int txor = t << 3;
    const int apx = tid & 63;          // A-staging pixel
    const int akp = tid >> 6;          // A-staging kpair base (0..7), also +8

    float acc[16][4];

    // ---- prologue: TMA stages 0,1 ; stageA(0) ----
    if (tid == 0) {
        mbar_expect_tx(sbase + 0, B_STAGE_BYTES);
        bulk_copy(sbase + SM_B0, g_wB, B_STAGE_BYTES, sbase + 0);
        mbar_expect_tx(sbase + 8, B_STAGE_BYTES);
        bulk_copy(sbase + SM_B0 + B_STAGE_BYTES, g_wB + B_STAGE_W, B_STAGE_BYTES, sbase + 8);
    }
    {
        // stage 0 of tile c: tap=0 -> dy=-1, dx=-1, ic0=0
        const int y0 = c % 56, bb0 = c / 56;
        const float* xb = x + (size_t)bb0 * ICN * HW;
        u32* Ab = (u32*)(smem + SM_A0);
        const int gy = y0 - 1, gx = apx - 1;
        const bool ok = gy >= 0 && gx >= 0;
        const float* src = xb + (size_t)(2 * akp) * HW + gy * WW + gx;
        float v0 = ok ? src[0] : 0.0f;
        float v1 = ok ? src[HW] : 0.0f;
        float v2 = ok ? src[16 * HW] : 0.0f;
        float v3 = ok ? src[17 * HW] : 0.0f;
        Ab[apx * AP + akp] = pack_h2(v0, v1);
        Ab[apx * AP + akp + 8] = pack_h2(v2, v3);
    }

    // ---- main loop over global stages ----
    for (int gs = 0; gs < total; gs++) {
        const int s = gs % NST;
        const int gt = c + (gs / NST) * NCTA;
        const int y = gt % 56, bb = gt / 56;

        mbar_wait(sbase + (gs % 3) * 8, (gs / 3) & 1);
        __syncthreads();

        // prefetch B for gs+2
        if (tid == 0 && gs + 2 < total) {
            const int s2 = (gs + 2) % NST;
            const u32 mb = sbase + ((gs + 2) % 3) * 8;
            mbar_expect_tx(mb, B_STAGE_BYTES);
            bulk_copy(sbase + SM_B0 + ((gs + 2) % 3) * B_STAGE_BYTES,
                      g_wB + (size_t)s2 * B_STAGE_W, B_STAGE_BYTES, mb);
        }

        // early LDG for A(gs+1)
        float av0 = 0.f, av1 = 0.f, av2 = 0.f, av3 = 0.f;
        const bool doA = (gs + 1 < total);
        if (doA) {
            const int gs1 = gs + 1;
            const int s1 = gs1 % NST;
            const int gt1 = c + (gs1 / NST) * NCTA;
            const int y1 = gt1 % 56, bb1 = gt1 / 56;
            const int tap = s1 >> 2;
            const int dy = tap / 3 - 1, dx = tap % 3 - 1;
            const int ic0 = ((s1 & 3) << 5) + 2 * akp;
            const int gy = y1 + dy, gx = apx + dx;
            if ((unsigned)gy < 56u && (unsigned)gx < 56u) {
                const float* src = x + (size_t)bb1 * ICN * HW + (size_t)ic0 * HW + gy * WW + gx;
                av0 = src[0];
                av1 = src[HW];
                av2 = src[16 * HW];
                av3 = src[17 * HW];
            }
        }

        if (s == 0) {
#pragma unroll
            for (int i = 0; i < 16; i++)
#pragma unroll
                for (int j = 0; j < 4; j++) acc[i][j] = 0.0f;
        }

        // ---- MMAs for stage gs (32 kc = 2 k16-steps) ----
        const u32* Bb = (const u32*)(smem + SM_B0 + (gs % 3) * B_STAGE_BYTES);
        const u32* Ab = (const u32*)(smem + SM_A0 + (gs & 1) * A_BUF_BYTES);
#pragma unroll
        for (int ks = 0; ks < 2; ks++) {
            const int ak = ks * 8 + t;
            u32 a0 = Ab[arow0 + ak];
            u32 a1 = Ab[arow1 + ak];
            u32 a2 = Ab[arow0 + ak + 4];
            u32 a3 = Ab[arow1 + ak + 4];
            const u32* b0p = Bb + (ks * 8 + t) * 512 + bcol;
            const u32* b1p = b0p + 4 * 512;
#pragma unroll
            for (int nt = 0; nt < 16; nt++) {
                const int off = (nt << 3) ^ txor;
                mma_f16(acc[nt][0], acc[nt][1], acc[nt][2], acc[nt][3],
                        a0, a1, a2, a3, b0p[off], b1p[off]);
            }
        }

        // store staged A(gs+1)
        if (doA) {
            u32* Ab1 = (u32*)(smem + SM_A0 + ((gs + 1) & 1) * A_BUF_BYTES);
            Ab1[apx * AP + akp] = pack_h2(av0, av1);
            Ab1[apx * AP + akp + 8] = pack_h2(av2, av3);
        }

        // ---- epilogue at tile end ----
        if (s == NST - 1) {
            __syncthreads();
            float* part = (float*)(smem + SM_PART);
            const int px0 = warp_m * 16 + g, px1 = px0 + 8;
            const float cw0 = g_cw[warp_n * HW + y * WW + px0];
            const float cw1 = (px1 < 56) ? g_cw[warp_n * HW + y * WW + px1] : 0.0f;
#pragma unroll
            for (int pass = 0; pass < 4; pass++) {
                if (warp_n == pass) {
#pragma unroll
                    for (int nt = 0; nt < 16; nt++) {
                        const int oc = nt * 8 + 2 * t;
                        float* p0 = &part[px0 * 132 + oc];
                        float* p1 = &part[px1 * 132 + oc];
                        if (pass == 0) {
                            p0[0] = cw0 * acc[nt][0]; p0[1] = cw0 * acc[nt][1];
                            p1[0] = cw1 * acc[nt][2]; p1[1] = cw1 * acc[nt][3];
                        } else {
                            p0[0] += cw0 * acc[nt][0]; p0[1] += cw0 * acc[nt][1];
                            p1[0] += cw1 * acc[nt][2]; p1[1] += cw1 * acc[nt][3];
                        }
                    }
                }
                __syncthreads();
            }
            const float br = b_row[y];
            for (int idx = tid; idx < OCN * 56; idx += 512) {
                const int oc = idx / 56, xx = idx - oc * 56;
                out[((size_t)(bb * OCN + oc) * HH + y) * WW + xx] =
                    part[xx * 132 + oc] + br + b_col[xx] + b_ch[oc];
            }
        }
    }
}

// ---------------- launch ----------------
extern "C" void kernel_launch(void* const* d_in, const int* in_sizes, int n_in,
                              void* d_out, int out_size) {
    const float* x      = (const float*)d_in[0];  // [32,128,56,56]
    const float* w      = (const float*)d_in[1];  // [4,128,128,3,3]
    const float* cw_row = (const float*)d_in[2];  // [4,56,1]
    const float* cw_col = (const float*)d_in[3];  // [4,1,56]
    const float* b_row  = (const float*)d_in[4];  // [1,1,56,1]
    const float* b_col  = (const float*)d_in[5];  // [1,1,1,56]
    const float* b_ch   = (const float*)d_in[6];  // [1,128,1,1]
    float* out = (float*)d_out;

    cudaFuncSetAttribute(conv_mma_kernel,
                         cudaFuncAttributeMaxDynamicSharedMemorySize, SM_TOTAL);

    prep_cw_kernel<<<(HW + 255) / 256, 256>>>(cw_row, cw_col);
    prep_wB_kernel<<<(NST * B_STAGE_W + 255) / 256, 256>>>(w);
    conv_mma_kernel<<<NCTA, 512, SM_TOTAL>>>(x, out, b_row, b_col, b_ch);
}

// round 8
// speedup vs baseline: 1.9011x; 1.1860x over previous
#include <cuda_runtime.h>
#include <cuda_fp16.h>

typedef unsigned int u32;
typedef unsigned long long u64;

#define RANKS 4
#define OCN   128
#define ICN   128
#define HH    56
#define WW    56
#define HW    3136
#define NST   24                      // stages per tile (48 k each)
#define KPST  24                      // kpairs per stage
#define NTILES 1792
#define NCTA   148

#define B_STAGE_W (KPST*512)          // 12288 words = 49152 B
#define B_STAGE_BYTES 49152
#define AP    28                      // A row stride in words (bank-exhaustive for frag loads)
#define A_BUF_BYTES (64*AP*4)         // 7168

#define SM_B0 1024
#define SM_A0 (1024 + 3*B_STAGE_BYTES)         // 148480
#define SM_A1 (SM_A0 + A_BUF_BYTES)            // 155648
#define SM_PART (SM_A1 + A_BUF_BYTES)          // 162816
#define SM_TOTAL (SM_PART + 64*132*4)          // 196608

__device__ __align__(16) u32   g_wB[NST * B_STAGE_W];  // fp16x2, pre-swizzled smem image
__device__ __align__(16) float g_cw[RANKS * HW];       // softmax combine weights

// ---------------- helpers ----------------
__device__ __forceinline__ u32 smem_u32(const void* p) {
    u32 a;
    asm("{ .reg .u64 t; cvta.to.shared.u64 t, %1; cvt.u32.u64 %0, t; }" : "=r"(a) : "l"(p));
    return a;
}
__device__ __forceinline__ u32 pack_h2(float lo, float hi) {
    __half2 h = __floats2half2_rn(lo, hi);
    return *(u32*)&h;
}
__device__ __forceinline__ void mbar_init(u32 addr, u32 cnt) {
    asm volatile("mbarrier.init.shared.b64 [%0], %1;" :: "r"(addr), "r"(cnt) : "memory");
}
__device__ __forceinline__ void mbar_expect_tx(u32 addr, u32 bytes) {
    asm volatile("mbarrier.arrive.expect_tx.shared.b64 _, [%0], %1;" :: "r"(addr), "r"(bytes) : "memory");
}
__device__ __forceinline__ void mbar_wait(u32 addr, int phase) {
    asm volatile(
        "{\n\t.reg .pred P;\n"
        "WL_%=:\n\t"
        "mbarrier.try_wait.parity.acquire.cta.shared::cta.b64 P, [%0], %1, 0x989680;\n\t"
        "@P bra.uni WD_%=;\n\t"
        "bra.uni WL_%=;\n\t"
        "WD_%=:\n\t}"
        :: "r"(addr), "r"((u32)phase) : "memory");
}
__device__ __forceinline__ void bulk_copy(u32 dst, const void* src, u32 bytes, u32 mbar) {
    asm volatile(
        "cp.async.bulk.shared::cluster.global.mbarrier::complete_tx::bytes [%0], [%1], %2, [%3];"
        :: "r"(dst), "l"(src), "r"(bytes), "r"(mbar) : "memory");
}
__device__ __forceinline__ void mma_f16(float& d0, float& d1, float& d2, float& d3,
                                        u32 a0, u32 a1, u32 a2, u32 a3, u32 b0, u32 b1) {
    asm volatile(
        "mma.sync.aligned.m16n8k16.row.col.f32.f16.f16.f32 "
        "{%0,%1,%2,%3}, {%4,%5,%6,%7}, {%8,%9}, {%0,%1,%2,%3};"
        : "+f"(d0), "+f"(d1), "+f"(d2), "+f"(d3)
        : "r"(a0), "r"(a1), "r"(a2), "r"(a3), "r"(b0), "r"(b1));
}

// ---------------- prep kernels ----------------
__global__ void prep_cw_kernel(const float* __restrict__ cw_row,
                               const float* __restrict__ cw_col) {
    int idx = blockIdx.x * blockDim.x + threadIdx.x;
    if (idx >= HW) return;
    int y = idx / WW, x = idx % WW;
    float v0 = cw_row[0 * HH + y] + cw_col[0 * WW + x];
    float v1 = cw_row[1 * HH + y] + cw_col[1 * WW + x];
    float v2 = cw_row[2 * HH + y] + cw_col[2 * WW + x];
    float v3 = cw_row[3 * HH + y] + cw_col[3 * WW + x];
    float m = fmaxf(fmaxf(v0, v1), fmaxf(v2, v3));
    float e0 = expf(v0 - m), e1 = expf(v1 - m), e2 = expf(v2 - m), e3 = expf(v3 - m);
    float inv = 1.0f / (e0 + e1 + e2 + e3);
    g_cw[0 * HW + idx] = e0 * inv;
    g_cw[1 * HW + idx] = e1 * inv;
    g_cw[2 * HW + idx] = e2 * inv;
    g_cw[3 * HW + idx] = e3 * inv;
}

// Weights -> fp16 pairs in swizzled smem image.
// Global k = s*48 + 2*kp + {0,1}; tap = k>>7, ic = k&127 (pair shares tap).
// smem word (kp, n): kp*512 + (n ^ ((kp&3)<<3)),  n = rank*128 + oc.
__global__ void prep_wB_kernel(const float* __restrict__ w) {
    int idx = blockIdx.x * blockDim.x + threadIdx.x;
    if (idx >= NST * B_STAGE_W) return;
    int n  = idx & 511;
    int kp = (idx >> 9) % KPST;
    int s  = idx / (512 * KPST);
    int r  = n >> 7, oc = n & 127;
    int k0 = s * 48 + 2 * kp;
    int tap = k0 >> 7;
    int ic  = k0 & 127;
    const float* wp = w + (((size_t)r * OCN + oc) * ICN + ic) * 9 + tap;
    g_wB[(size_t)s * B_STAGE_W + kp * 512 + (n ^ ((kp & 3) << 3))] = pack_h2(wp[0], wp[9]);
}

// ---------------- A staging (im2col, per-kpair tap decode) ----------------
__device__ __forceinline__ void ldgA(float* av, const float* __restrict__ x,
                                     int bb, int y, int s, int px, int kpb) {
#pragma unroll
    for (int j = 0; j < 6; j++) {
        const int kp = kpb + j * 4;
        const int k0 = s * 48 + 2 * kp;
        const int tap = k0 >> 7;
        const int ic  = k0 & 127;
        const int gy = y + tap / 3 - 1;
        const int gx = px + tap % 3 - 1;
        if ((unsigned)gy < 56u && (unsigned)gx < 56u) {
            const float* src = x + (size_t)bb * ICN * HW + (size_t)ic * HW + gy * WW + gx;
            av[2 * j]     = src[0];
            av[2 * j + 1] = src[HW];
        } else {
            av[2 * j] = 0.0f;
            av[2 * j + 1] = 0.0f;
        }
    }
}
__device__ __forceinline__ void stsA(u32* Ab, const float* av, int px, int kpb) {
#pragma unroll
    for (int j = 0; j < 6; j++)
        Ab[px * AP + kpb + j * 4] = pack_h2(av[2 * j], av[2 * j + 1]);
}

// ---------------- main persistent mma kernel ----------------
// grid 148 CTAs x 256 threads; CTA c handles tiles c, c+148, ...
// tile -> bb = tile/56, y = tile%56.  8 warps = 2 warp_m x 4 warp_n(=rank).
// warp: 32 px (two m16 groups) x 128 n.
__global__ __launch_bounds__(256, 1)
void conv_mma_kernel(const float* __restrict__ x, float* __restrict__ out,
                     const float* __restrict__ b_row, const float* __restrict__ b_col,
                     const float* __restrict__ b_ch) {
    extern __shared__ char smem[];
    const u32 sbase = smem_u32(smem);
    const int tid = threadIdx.x;
    const int wid = tid >> 5, lane = tid & 31;
    const int warp_m = wid & 1, warp_n = wid >> 1;
    const int g = lane >> 2, t = lane & 3;
    const int c = blockIdx.x;

    const int ntile = (NTILES - c + NCTA - 1) / NCTA;
    const int total = ntile * NST;

    if (tid == 0) {
        mbar_init(sbase + 0, 1);
        mbar_init(sbase + 8, 1);
        mbar_init(sbase + 16, 1);
    }
    __syncthreads();

    // fragment / staging constants
    const int ar0 = (warp_m * 32 + g) * AP;        // mg0 row g
    const int bcol = warp_n * 128 + g;
    const int txor = t << 3;
    const int apx = tid & 63;
    const int akpb = tid >> 6;                     // 0..3

    float acc[2][16][4];

    // ---- prologue: TMA stages 0,1 ; stageA(0) ----
    if (tid == 0) {
        mbar_expect_tx(sbase + 0, B_STAGE_BYTES);
        bulk_copy(sbase + SM_B0, g_wB, B_STAGE_BYTES, sbase + 0);
        mbar_expect_tx(sbase + 8, B_STAGE_BYTES);
        bulk_copy(sbase + SM_B0 + B_STAGE_BYTES, g_wB + B_STAGE_W, B_STAGE_BYTES, sbase + 8);
    }
    {
        float av[12];
        ldgA(av, x, c / 56, c % 56, 0, apx, akpb);
        stsA((u32*)(smem + SM_A0), av, apx, akpb);
    }

    // ---- main loop over global stages ----
    for (int gs = 0; gs < total; gs++) {
        const int s = gs % NST;
        const int gt = c + (gs / NST) * NCTA;
        const int y = gt % 56, bb = gt / 56;

        mbar_wait(sbase + (gs % 3) * 8, (gs / 3) & 1);
        __syncthreads();

        // prefetch B for gs+2
        if (tid == 0 && gs + 2 < total) {
            const int s2 = (gs + 2) % NST;
            const u32 mb = sbase + ((gs + 2) % 3) * 8;
            mbar_expect_tx(mb, B_STAGE_BYTES);
            bulk_copy(sbase + SM_B0 + ((gs + 2) % 3) * B_STAGE_BYTES,
                      g_wB + (size_t)s2 * B_STAGE_W, B_STAGE_BYTES, mb);
        }

        // early LDG for A(gs+1)
        float av[12];
        const bool doA = (gs + 1 < total);
        if (doA) {
            const int gs1 = gs + 1;
            const int gt1 = c + (gs1 / NST) * NCTA;
            ldgA(av, x, gt1 / 56, gt1 % 56, gs1 % NST, apx, akpb);
        }

        if (s == 0) {
#pragma unroll
            for (int m = 0; m < 2; m++)
#pragma unroll
                for (int i = 0; i < 16; i++)
#pragma unroll
                    for (int j = 0; j < 4; j++) acc[m][i][j] = 0.0f;
        }

        // ---- MMAs for stage gs (48 kc = 3 k16-steps, 2 m16 groups) ----
        const u32* Bb = (const u32*)(smem + SM_B0 + (gs % 3) * B_STAGE_BYTES);
        const u32* Ab = (const u32*)(smem + SM_A0 + (gs & 1) * A_BUF_BYTES);
#pragma unroll
        for (int ks = 0; ks < 3; ks++) {
            const int ak = ks * 8 + t;
            u32 a00 = Ab[ar0 + ak];
            u32 a01 = Ab[ar0 + 8 * AP + ak];
            u32 a02 = Ab[ar0 + ak + 4];
            u32 a03 = Ab[ar0 + 8 * AP + ak + 4];
            u32 a10 = Ab[ar0 + 16 * AP + ak];
            u32 a11 = Ab[ar0 + 24 * AP + ak];
            u32 a12 = Ab[ar0 + 16 * AP + ak + 4];
            u32 a13 = Ab[ar0 + 24 * AP + ak + 4];
            const u32* b0p = Bb + ak * 512 + bcol;
            const u32* b1p = b0p + 4 * 512;
#pragma unroll
            for (int nt = 0; nt < 16; nt++) {
                const int off = (nt << 3) ^ txor;
                const u32 b0 = b0p[off], b1 = b1p[off];
                mma_f16(acc[0][nt][0], acc[0][nt][1], acc[0][nt][2], acc[0][nt][3],
                        a00, a01, a02, a03, b0, b1);
                mma_f16(acc[1][nt][0], acc[1][nt][1], acc[1][nt][2], acc[1][nt][3],
                        a10, a11, a12, a13, b0, b1);
            }
        }

        // store staged A(gs+1)
        if (doA)
            stsA((u32*)(smem + SM_A0 + ((gs + 1) & 1) * A_BUF_BYTES), av, apx, akpb);

        // ---- epilogue at tile end ----
        if (s == NST - 1) {
            __syncthreads();
            float* part = (float*)(smem + SM_PART);
#pragma unroll
            for (int pass = 0; pass < 4; pass++) {
                if (warp_n == pass) {
#pragma unroll
                    for (int mg = 0; mg < 2; mg++) {
                        const int px0 = warp_m * 32 + mg * 16 + g;
                        const int px1 = px0 + 8;
                        const float cw0 = g_cw[warp_n * HW + y * WW + px0];
                        const float cw1 = (px1 < 56) ? g_cw[warp_n * HW + y * WW + px1] : 0.0f;
#pragma unroll
                        for (int nt = 0; nt < 16; nt++) {
                            const int oc = nt * 8 + 2 * t;
                            float* p0 = &part[px0 * 132 + oc];
                            float* p1 = &part[px1 * 132 + oc];
                            if (pass == 0) {
                                p0[0] = cw0 * acc[mg][nt][0]; p0[1] = cw0 * acc[mg][nt][1];
                                p1[0] = cw1 * acc[mg][nt][2]; p1[1] = cw1 * acc[mg][nt][3];
                            } else {
                                p0[0] += cw0 * acc[mg][nt][0]; p0[1] += cw0 * acc[mg][nt][1];
                                p1[0] += cw1 * acc[mg][nt][2]; p1[1] += cw1 * acc[mg][nt][3];
                            }
                        }
                    }
                }
                __syncthreads();
            }
            const float br = b_row[y];
            for (int idx = tid; idx < OCN * 56; idx += 256) {
                const int oc = idx / 56, xx = idx - oc * 56;
                out[((size_t)(bb * OCN + oc) * HH + y) * WW + xx] =
                    part[xx * 132 + oc] + br + b_col[xx] + b_ch[oc];
            }
        }
    }
}

// ---------------- launch ----------------
extern "C" void kernel_launch(void* const* d_in, const int* in_sizes, int n_in,
                              void* d_out, int out_size) {
    const float* x      = (const float*)d_in[0];  // [32,128,56,56]
    const float* w      = (const float*)d_in[1];  // [4,128,128,3,3]
    const float* cw_row = (const float*)d_in[2];  // [4,56,1]
    const float* cw_col = (const float*)d_in[3];  // [4,1,56]
    const float* b_row  = (const float*)d_in[4];  // [1,1,56,1]
    const float* b_col  = (const float*)d_in[5];  // [1,1,1,56]
    const float* b_ch   = (const float*)d_in[6];  // [1,128,1,1]
    float* out = (float*)d_out;

    cudaFuncSetAttribute(conv_mma_kernel,
                         cudaFuncAttributeMaxDynamicSharedMemorySize, SM_TOTAL);

    prep_cw_kernel<<<(HW + 255) / 256, 256>>>(cw_row, cw_col);
    prep_wB_kernel<<<(NST * B_STAGE_W + 255) / 256, 256>>>(w);
    conv_mma_kernel<<<NCTA, 256, SM_TOTAL>>>(x, out, b_row, b_col, b_ch);
}